// round 17
// baseline (speedup 1.0000x reference)
#include <cuda_runtime.h>
#include <cstdint>

// Problem constants (fixed by the reference: N=64, T=2048, F=256)
#define CBS_N 64
#define CBS_T 2048
#define CBS_F 256
#define CBS_F4 (CBS_F / 4)     // 64 float4 per (n, t) row
#define THREADS_PER_ROW 32      // each thread: 2 float4, INTERLEAVED stride 32
#define ROWS_PER_BLOCK (256 / THREADS_PER_ROW)   // 8

// GRANULARITY PROBE: 2 interleaved float4/thread + __stcs.
//
// Established (bench steady state; ncu is flushed and can't see it):
//  - __stcs >> plain/stwt stores (26.6-28.7 vs 29.2-30.7).
//  - Within stcs, FINER granularity wins:
//      1 f4/thread: 26.6, 25.1 (mean 25.8)  <- replicated session best
//      4 f4/thread: 27.1, 27.4, 27.4 (mean 27.3)
//    Mechanism: more warps/byte -> finer store interleave across LTS
//    slices -> smoother evict-first drain; steady-state reads are L2 hits
//    (bench 25.1 < flushed ncu 25.9 proves residency).
//  - This round probes the interior: 2 f4/thread halves issue cost vs 1
//    while staying fine-grained. Fallback = exact R16 kernel (25.1).

__device__ __forceinline__ int imax_(int a, int b) { return a > b ? a : b; }
__device__ __forceinline__ int imin_(int a, int b) { return a < b ? a : b; }

// grid = (T/8, N) = (256, 64), block = 256.
__global__ void __launch_bounds__(256)
chunk_by_slices_g2_kernel(const float4* __restrict__ x,
                          const int* __restrict__ slices,
                          const int* __restrict__ lens,
                          float4* __restrict__ out,
                          float* __restrict__ out_lens) {
    const int n = blockIdx.y;

    // Per-row parameters; uniform across the block -> L1 broadcast.
    const int s = slices[2 * n];
    const int e = slices[2 * n + 1];
    const int chunk_len = imax_(e - s, 0);
    const int left_pad  = (chunk_len == 0) ? 0 : imax_(-s, 0);
    const int start_    = imax_(s, 0);
    const int end_      = imin_(e, lens[n]);
    const int slice_len = imax_(end_ - start_, 0);

    // Fused chunk_lens write (float32-encoded): one thread per n.
    if (blockIdx.x == 0 && threadIdx.x == 0) {
        out_lens[n] = (float)chunk_len;
    }

    const int t  = blockIdx.x * ROWS_PER_BLOCK + (threadIdx.x >> 5);
    const int f0 = threadIdx.x & 31;   // interleaved: f0, f0+32

    const bool valid = (t >= left_pad) && (t < left_pad + slice_len);

    int src = start_ + t - left_pad;
    src = imin_(imax_(src, 0), CBS_T - 1);

    float4 v0, v1;
    if (valid) {
        const float4* xr = &x[(n * CBS_T + src) * CBS_F4 + f0];
        v0 = __ldg(xr + 0);
        v1 = __ldg(xr + 32);
    } else {
        v0 = v1 = make_float4(0.f, 0.f, 0.f, 0.f);
    }

    float4* op = &out[(n * CBS_T + t) * CBS_F4 + f0];
    __stcs(op + 0,  v0);
    __stcs(op + 32, v1);
}

extern "C" void kernel_launch(void* const* d_in, const int* in_sizes, int n_in,
                              void* d_out, int out_size) {
    const float4* x      = (const float4*)d_in[0];
    const int*    slices = (const int*)d_in[1];
    const int*    lens   = (const int*)d_in[2];
    float4*       out    = (float4*)d_out;

    const long long chunks_elems = (long long)CBS_N * CBS_T * CBS_F;
    float* out_lens = ((float*)d_out) + chunks_elems;

    dim3 block(256);
    dim3 grid(CBS_T / ROWS_PER_BLOCK, CBS_N);  // (256, 64)
    chunk_by_slices_g2_kernel<<<grid, block>>>(x, slices, lens, out, out_lens);
}